// round 2
// baseline (speedup 1.0000x reference)
#include <cuda_runtime.h>
#include <cstdint>

#define BB 2048
#define TT 512
#define DD 178
#define HH 5
#define NG 20          // 4*H
#define KP 184         // padded K (23*8)
#define KC 8           // k-chunk
#define NCH 23
#define ROWS_CTA 1024
#define THR1 128

// 84 MB scratch for gate pre-activations, layout [b][t][unit j][i,f,g,o]
__device__ float g_xg[(size_t)BB * TT * NG];

__device__ __forceinline__ unsigned long long pack2(float lo, float hi) {
    unsigned long long r;
    asm("mov.b64 %0, {%1,%2};" : "=l"(r) : "f"(lo), "f"(hi));
    return r;
}
__device__ __forceinline__ void fma2(unsigned long long& d, unsigned long long a,
                                     unsigned long long b) {
    asm("fma.rn.f32x2 %0, %1, %2, %0;" : "+l"(d) : "l"(a), "l"(b));
}
__device__ __forceinline__ void unpack2(unsigned long long v, float& lo, float& hi) {
    asm("mov.b64 {%0,%1}, %2;" : "=f"(lo), "=f"(hi) : "l"(v));
}

// ---------------------------------------------------------------------------
// Phase 1: xg[row][perm(g)] = sum_k x[row][k] * w_ih[g][k]
// row = b*512 + t. Each CTA: 1024 rows. Each thread: 8 rows x 20 gates,
// rows paired into f32x2 accumulators. Weights duplicated (w,w) in smem.
// x streamed via 2-stage cp.async pipeline, tile[row][k] padded to 10 floats.
// ---------------------------------------------------------------------------
extern "C" __global__ void __launch_bounds__(THR1)
gate_gemm(const float* __restrict__ x, const float* __restrict__ w_ih) {
    extern __shared__ char smem[];
    float* xb0 = (float*)smem;
    float* xb1 = xb0 + ROWS_CTA * 10;
    unsigned long long* wsm = (unsigned long long*)(smem + 2 * ROWS_CTA * 10 * 4);

    const int tid = threadIdx.x;
    const size_t row0 = (size_t)blockIdx.x * ROWS_CTA;

    // fill padded duplicated weights, layout [k][g]
    for (int i = tid; i < KP * NG; i += THR1) {
        int k = i / NG, g = i % NG;
        float v = (k < DD) ? w_ih[g * DD + k] : 0.0f;
        wsm[i] = pack2(v, v);
    }

    unsigned xsb0 = (unsigned)__cvta_generic_to_shared(xb0);
    unsigned xsb1 = (unsigned)__cvta_generic_to_shared(xb1);

    const int lane4 = tid & 3;   // which 8B piece of the 32B k-chunk
    const int rowq  = tid >> 2;  // 0..31

    auto load_chunk = [&](int c) {
        unsigned xsb = (c & 1) ? xsb1 : xsb0;
        int k = c * KC + lane4 * 2;
        if (k < DD) {
            const float* sp = x + row0 * DD + k;
            unsigned dcol = (unsigned)(lane4 * 2) << 2;
#pragma unroll 4
            for (int r = 0; r < 32; ++r) {
                int row = rowq + r * 32;
                unsigned dst = xsb + (unsigned)(row * 40) + dcol;  // 10 floats/row
                const float* src = sp + (size_t)row * DD;
                asm volatile("cp.async.ca.shared.global [%0], [%1], 8;" ::
                             "r"(dst), "l"(src));
            }
        }
        asm volatile("cp.async.commit_group;");
    };

    load_chunk(0);
    load_chunk(1);

    unsigned long long acc[4 * NG];
#pragma unroll
    for (int i = 0; i < 4 * NG; ++i) acc[i] = 0ULL;

    for (int c = 0; c < NCH; ++c) {
        if (c == NCH - 1) asm volatile("cp.async.wait_group 0;");
        else              asm volatile("cp.async.wait_group 1;");
        __syncthreads();
        const float* xbc = (c & 1) ? xb1 : xb0;
        const unsigned long long* wk = wsm + c * KC * NG;
#pragma unroll
        for (int kk = 0; kk < KC; ++kk) {
            unsigned long long xp[4];
#pragma unroll
            for (int p = 0; p < 4; ++p) {
                float lo = xbc[(tid + 256 * p) * 10 + kk];
                float hi = xbc[(tid + 256 * p + 128) * 10 + kk];
                xp[p] = pack2(lo, hi);
            }
#pragma unroll
            for (int g = 0; g < NG; ++g) {
                unsigned long long wv = wk[kk * NG + g];
#pragma unroll
                for (int p = 0; p < 4; ++p) fma2(acc[p * NG + g], xp[p], wv);
            }
        }
        __syncthreads();
        if (c + 2 < NCH) load_chunk(c + 2);
    }

    // epilogue: write gates in phase-2-friendly order [row][j][i,f,g,o]
#pragma unroll
    for (int m = 0; m < 8; ++m) {
        size_t R = row0 + tid + 128 * m;
        float gs[NG];
#pragma unroll
        for (int g = 0; g < NG; ++g) {
            float lo, hi;
            unpack2(acc[(m >> 1) * NG + g], lo, hi);
            gs[g] = (m & 1) ? hi : lo;
        }
        float4* op = (float4*)(g_xg + R * NG);
#pragma unroll
        for (int j = 0; j < HH; ++j)
            op[j] = make_float4(gs[j], gs[j + HH], gs[j + 2 * HH], gs[j + 3 * HH]);
    }
}

// ---------------------------------------------------------------------------
// Phase 2: 512-step recurrence. 5 lanes per sequence (one hidden unit each),
// 4 sequences per warp (8-lane groups, lanes 5-7 idle-compute).
// ---------------------------------------------------------------------------
__device__ __forceinline__ float sigm(float xv) {
    float e, r;
    asm("ex2.approx.f32 %0, %1;" : "=f"(e) : "f"(-1.4426950408889634f * xv));
    asm("rcp.approx.f32 %0, %1;" : "=f"(r) : "f"(1.0f + e));
    return r;
}
__device__ __forceinline__ float tanha(float xv) {
    float e, r;
    asm("ex2.approx.f32 %0, %1;" : "=f"(e) : "f"(-2.8853900817779268f * xv));
    asm("rcp.approx.f32 %0, %1;" : "=f"(r) : "f"(1.0f + e));
    return fmaf(2.0f, r, -1.0f);
}

extern "C" __global__ void __launch_bounds__(128)
lstm_rec(const float* __restrict__ w_hh, const float* __restrict__ b_ih,
         const float* __restrict__ b_hh, const float* __restrict__ w_fc,
         const float* __restrict__ b_fc, float* __restrict__ out) {
    const int lane = threadIdx.x & 31;
    const int warp = threadIdx.x >> 5;
    const int s    = lane >> 3;
    const int j0   = lane & 7;
    const int j    = (j0 < HH) ? j0 : 0;
    const int seq  = (blockIdx.x * 4 + warp) * 4 + s;

    float wi[HH], wf[HH], wg[HH], wo[HH];
#pragma unroll
    for (int m = 0; m < HH; ++m) {
        wi[m] = w_hh[j * HH + m];
        wf[m] = w_hh[(HH + j) * HH + m];
        wg[m] = w_hh[(2 * HH + j) * HH + m];
        wo[m] = w_hh[(3 * HH + j) * HH + m];
    }
    const float bi  = b_ih[j] + b_hh[j];
    const float bff = b_ih[HH + j] + b_hh[HH + j];
    const float bg  = b_ih[2 * HH + j] + b_hh[2 * HH + j];
    const float bo  = b_ih[3 * HH + j] + b_hh[3 * HH + j];

    const float4* gp = (const float4*)g_xg + (size_t)seq * TT * (NG / 4) + j;

    float c = 0.0f, h = 0.0f;
    float hv[HH];
#pragma unroll
    for (int m = 0; m < HH; ++m) hv[m] = 0.0f;

    float4 nxt = gp[0];
    for (int t = 0; t < TT; ++t) {
        float4 cur = nxt;
        if (t + 1 < TT) nxt = gp[(t + 1) * (NG / 4)];
        float pi = cur.x + bi, pf = cur.y + bff, pg = cur.z + bg, po = cur.w + bo;
#pragma unroll
        for (int m = 0; m < HH; ++m) {
            pi = fmaf(hv[m], wi[m], pi);
            pf = fmaf(hv[m], wf[m], pf);
            pg = fmaf(hv[m], wg[m], pg);
            po = fmaf(hv[m], wo[m], po);
        }
        float ig = sigm(pi) * tanha(pg);
        c = fmaf(sigm(pf), c, ig);
        h = sigm(po) * tanha(c);
        const int base = lane & ~7;
#pragma unroll
        for (int m = 0; m < HH; ++m)
            hv[m] = __shfl_sync(0xffffffffu, h, base + m);
    }

    if (j0 < HH) {
        float acc = b_fc[j];
#pragma unroll
        for (int m = 0; m < HH; ++m)
            acc = fmaf(fmaxf(hv[m], 0.0f), w_fc[j * HH + m], acc);
        out[(size_t)seq * HH + j] = acc;
    }
}

extern "C" void kernel_launch(void* const* d_in, const int* in_sizes, int n_in,
                              void* d_out, int out_size) {
    const float* x    = (const float*)d_in[0];
    const float* w_ih = (const float*)d_in[1];
    const float* w_hh = (const float*)d_in[2];
    const float* b_ih = (const float*)d_in[3];
    const float* b_hh = (const float*)d_in[4];
    const float* w_fc = (const float*)d_in[5];
    const float* b_fc = (const float*)d_in[6];

    const int smem = 2 * ROWS_CTA * 10 * 4 + KP * NG * 8;  // 111360 B
    cudaFuncSetAttribute(gate_gemm, cudaFuncAttributeMaxDynamicSharedMemorySize, smem);

    gate_gemm<<<(BB * TT) / ROWS_CTA, THR1, smem>>>(x, w_ih);
    lstm_rec<<<BB / 16, 128>>>(w_hh, b_ih, b_hh, w_fc, b_fc, (float*)d_out);
}

// round 3
// speedup vs baseline: 1.0235x; 1.0235x over previous
#include <cuda_runtime.h>
#include <cstdint>

#define BB 2048
#define TT 512
#define DD 178
#define HH 5
#define NG 20          // 4*H
#define KP 184         // padded K (23*8)
#define KC 8           // k-chunk
#define NCH 23
#define ROWS_CTA 1024
#define THR1 128

// 84 MB scratch for gate pre-activations, layout [b][t][unit j][i,f,g,o]
__device__ float g_xg[(size_t)BB * TT * NG];

__device__ __forceinline__ unsigned long long pack2(float lo, float hi) {
    unsigned long long r;
    asm("mov.b64 %0, {%1,%2};" : "=l"(r) : "f"(lo), "f"(hi));
    return r;
}
__device__ __forceinline__ void fma2(unsigned long long& d, unsigned long long a,
                                     unsigned long long b) {
    asm("fma.rn.f32x2 %0, %1, %2, %0;" : "+l"(d) : "l"(a), "l"(b));
}
__device__ __forceinline__ void unpack2(unsigned long long v, float& lo, float& hi) {
    asm("mov.b64 {%0,%1}, %2;" : "=f"(lo), "=f"(hi) : "l"(v));
}

// ---------------------------------------------------------------------------
// Phase 1: xg[row][perm(g)] = sum_k x[row][k] * w_ih[g][k]
// row = b*512 + t. Each CTA: 1024 rows. Each thread: 8 rows x 20 gates,
// rows paired into f32x2 accumulators. Weights duplicated (w,w) in smem.
// x streamed via 2-stage cp.async pipeline, tile[row][k] padded to 10 floats.
// ---------------------------------------------------------------------------
extern "C" __global__ void __launch_bounds__(THR1)
gate_gemm(const float* __restrict__ x, const float* __restrict__ w_ih) {
    extern __shared__ char smem[];
    float* xb0 = (float*)smem;
    float* xb1 = xb0 + ROWS_CTA * 10;
    unsigned long long* wsm = (unsigned long long*)(smem + 2 * ROWS_CTA * 10 * 4);

    const int tid = threadIdx.x;
    const size_t row0 = (size_t)blockIdx.x * ROWS_CTA;

    // fill padded duplicated weights, layout [k][g]
    for (int i = tid; i < KP * NG; i += THR1) {
        int k = i / NG, g = i % NG;
        float v = (k < DD) ? w_ih[g * DD + k] : 0.0f;
        wsm[i] = pack2(v, v);
    }

    unsigned xsb0 = (unsigned)__cvta_generic_to_shared(xb0);
    unsigned xsb1 = (unsigned)__cvta_generic_to_shared(xb1);

    const int lane4 = tid & 3;   // which 8B piece of the 32B k-chunk
    const int rowq  = tid >> 2;  // 0..31

    auto load_chunk = [&](int c) {
        unsigned xsb = (c & 1) ? xsb1 : xsb0;
        int k = c * KC + lane4 * 2;
        if (k < DD) {
            const float* sp = x + row0 * DD + k;
            unsigned dcol = (unsigned)(lane4 * 2) << 2;
#pragma unroll 4
            for (int r = 0; r < 32; ++r) {
                int row = rowq + r * 32;
                unsigned dst = xsb + (unsigned)(row * 40) + dcol;  // 10 floats/row
                const float* src = sp + (size_t)row * DD;
                asm volatile("cp.async.ca.shared.global [%0], [%1], 8;" ::
                             "r"(dst), "l"(src));
            }
        }
        asm volatile("cp.async.commit_group;");
    };

    load_chunk(0);
    load_chunk(1);

    unsigned long long acc[4 * NG];
#pragma unroll
    for (int i = 0; i < 4 * NG; ++i) acc[i] = 0ULL;

    for (int c = 0; c < NCH; ++c) {
        if (c == NCH - 1) asm volatile("cp.async.wait_group 0;");
        else              asm volatile("cp.async.wait_group 1;");
        __syncthreads();
        const float* xbc = (c & 1) ? xb1 : xb0;
        const unsigned long long* wk = wsm + c * KC * NG;
#pragma unroll
        for (int kk = 0; kk < KC; ++kk) {
            unsigned long long xp[4];
#pragma unroll
            for (int p = 0; p < 4; ++p) {
                float lo = xbc[(tid + 256 * p) * 10 + kk];
                float hi = xbc[(tid + 256 * p + 128) * 10 + kk];
                xp[p] = pack2(lo, hi);
            }
#pragma unroll
            for (int g = 0; g < NG; ++g) {
                unsigned long long wv = wk[kk * NG + g];
#pragma unroll
                for (int p = 0; p < 4; ++p) fma2(acc[p * NG + g], xp[p], wv);
            }
        }
        __syncthreads();
        if (c + 2 < NCH) load_chunk(c + 2);
    }

    // epilogue: write gates in phase-2-friendly order [row][j][i,f,g,o]
#pragma unroll
    for (int m = 0; m < 8; ++m) {
        size_t R = row0 + tid + 128 * m;
        float gs[NG];
#pragma unroll
        for (int g = 0; g < NG; ++g) {
            float lo, hi;
            unpack2(acc[(m >> 1) * NG + g], lo, hi);
            gs[g] = (m & 1) ? hi : lo;
        }
        float4* op = (float4*)(g_xg + R * NG);
#pragma unroll
        for (int j = 0; j < HH; ++j)
            op[j] = make_float4(gs[j], gs[j + HH], gs[j + 2 * HH], gs[j + 3 * HH]);
    }
}

// ---------------------------------------------------------------------------
// Phase 2: 512-step recurrence. 5 lanes per sequence (one hidden unit each),
// 4 sequences per warp (8-lane groups, lanes 5-7 idle-compute).
// ---------------------------------------------------------------------------
__device__ __forceinline__ float sigm(float xv) {
    float e, r;
    asm("ex2.approx.f32 %0, %1;" : "=f"(e) : "f"(-1.4426950408889634f * xv));
    asm("rcp.approx.f32 %0, %1;" : "=f"(r) : "f"(1.0f + e));
    return r;
}
__device__ __forceinline__ float tanha(float xv) {
    float e, r;
    asm("ex2.approx.f32 %0, %1;" : "=f"(e) : "f"(-2.8853900817779268f * xv));
    asm("rcp.approx.f32 %0, %1;" : "=f"(r) : "f"(1.0f + e));
    return fmaf(2.0f, r, -1.0f);
}

extern "C" __global__ void __launch_bounds__(128)
lstm_rec(const float* __restrict__ w_hh, const float* __restrict__ b_ih,
         const float* __restrict__ b_hh, const float* __restrict__ w_fc,
         const float* __restrict__ b_fc, float* __restrict__ out) {
    const int lane = threadIdx.x & 31;
    const int warp = threadIdx.x >> 5;
    const int s    = lane >> 3;
    const int j0   = lane & 7;
    const int j    = (j0 < HH) ? j0 : 0;
    const int seq  = (blockIdx.x * 4 + warp) * 4 + s;

    float wi[HH], wf[HH], wg[HH], wo[HH];
#pragma unroll
    for (int m = 0; m < HH; ++m) {
        wi[m] = w_hh[j * HH + m];
        wf[m] = w_hh[(HH + j) * HH + m];
        wg[m] = w_hh[(2 * HH + j) * HH + m];
        wo[m] = w_hh[(3 * HH + j) * HH + m];
    }
    const float bi  = b_ih[j] + b_hh[j];
    const float bff = b_ih[HH + j] + b_hh[HH + j];
    const float bg  = b_ih[2 * HH + j] + b_hh[2 * HH + j];
    const float bo  = b_ih[3 * HH + j] + b_hh[3 * HH + j];

    const float4* gp = (const float4*)g_xg + (size_t)seq * TT * (NG / 4) + j;

    float c = 0.0f, h = 0.0f;
    float hv[HH];
#pragma unroll
    for (int m = 0; m < HH; ++m) hv[m] = 0.0f;

    float4 nxt = gp[0];
    for (int t = 0; t < TT; ++t) {
        float4 cur = nxt;
        if (t + 1 < TT) nxt = gp[(t + 1) * (NG / 4)];
        float pi = cur.x + bi, pf = cur.y + bff, pg = cur.z + bg, po = cur.w + bo;
#pragma unroll
        for (int m = 0; m < HH; ++m) {
            pi = fmaf(hv[m], wi[m], pi);
            pf = fmaf(hv[m], wf[m], pf);
            pg = fmaf(hv[m], wg[m], pg);
            po = fmaf(hv[m], wo[m], po);
        }
        float ig = sigm(pi) * tanha(pg);
        c = fmaf(sigm(pf), c, ig);
        h = sigm(po) * tanha(c);
        const int base = lane & ~7;
#pragma unroll
        for (int m = 0; m < HH; ++m)
            hv[m] = __shfl_sync(0xffffffffu, h, base + m);
    }

    if (j0 < HH) {
        float acc = b_fc[j];
#pragma unroll
        for (int m = 0; m < HH; ++m)
            acc = fmaf(fmaxf(hv[m], 0.0f), w_fc[j * HH + m], acc);
        out[(size_t)seq * HH + j] = acc;
    }
}

extern "C" void kernel_launch(void* const* d_in, const int* in_sizes, int n_in,
                              void* d_out, int out_size) {
    const float* x    = (const float*)d_in[0];
    const float* w_ih = (const float*)d_in[1];
    const float* w_hh = (const float*)d_in[2];
    const float* b_ih = (const float*)d_in[3];
    const float* b_hh = (const float*)d_in[4];
    const float* w_fc = (const float*)d_in[5];
    const float* b_fc = (const float*)d_in[6];

    const int smem = 2 * ROWS_CTA * 10 * 4 + KP * NG * 8;  // 111360 B
    cudaFuncSetAttribute(gate_gemm, cudaFuncAttributeMaxDynamicSharedMemorySize, smem);

    gate_gemm<<<(BB * TT) / ROWS_CTA, THR1, smem>>>(x, w_ih);
    lstm_rec<<<BB / 16, 128>>>(w_hh, b_ih, b_hh, w_fc, b_fc, (float*)d_out);
}

// round 4
// speedup vs baseline: 2.3013x; 2.2486x over previous
#include <cuda_runtime.h>
#include <cstdint>

#define BB 2048
#define TT 512
#define DD 178
#define HH 5
#define NG 20
#define SUBROWS 128
#define SUBT 8
#define THR1 256
#define SUB_BYTES (SUBROWS * DD * 4)   // 91136 B, multiple of 16

typedef unsigned long long ull;

__device__ float g_xg[(size_t)BB * TT * NG];   // [b][t][j][i,f,g,o]

#define SM_MBAR 0
#define SM_W    16
#define SM_SC   (16 + 17088)
#define SM_XB0  27392
#define SM_XB1  (27392 + SUB_BYTES)
#define SM_TOT  (SM_XB1 + SUB_BYTES)   // 209664 B

__device__ __forceinline__ ull pack2(float lo, float hi) {
    ull r; asm("mov.b64 %0, {%1,%2};" : "=l"(r) : "f"(lo), "f"(hi)); return r;
}
__device__ __forceinline__ ull dup2(float v) {
    ull r; asm("mov.b64 %0, {%1,%1};" : "=l"(r) : "f"(v)); return r;
}
__device__ __forceinline__ void unpack2(ull v, float& lo, float& hi) {
    asm("mov.b64 {%0,%1}, %2;" : "=f"(lo), "=f"(hi) : "l"(v));
}
__device__ __forceinline__ void fma2(ull& d, ull a, ull b) {
    asm("fma.rn.f32x2 %0, %1, %2, %0;" : "+l"(d) : "l"(a), "l"(b));
}
__device__ __forceinline__ ull add2(ull a, ull b) {
    ull r; asm("add.rn.f32x2 %0, %1, %2;" : "=l"(r) : "l"(a), "l"(b)); return r;
}
__device__ __forceinline__ void mbar_wait(uint32_t mbar, uint32_t parity) {
    asm volatile(
        "{\n\t.reg .pred P;\nW%=:\n\t"
        "mbarrier.try_wait.parity.acquire.cta.shared::cta.b64 P, [%0], %1, 0x989680;\n\t"
        "@P bra D%=;\n\tbra W%=;\nD%=:\n\t}"
        :: "r"(mbar), "r"(parity) : "memory");
}

// Phase 1: xg = x @ w_ih.T  (M=1M, K=178, N=20). TMA-streamed x, f32x2 FMAs.
extern "C" __global__ void __launch_bounds__(THR1, 1)
gate_gemm(const float* __restrict__ x, const float* __restrict__ w_ih) {
    extern __shared__ char smem[];
    float* ws = (float*)(smem + SM_W);
    float* sc = (float*)(smem + SM_SC);
    const uint32_t smb = (uint32_t)__cvta_generic_to_shared(smem);
    const uint32_t mbar0 = smb + SM_MBAR, mbar1 = mbar0 + 8;
    const int tid = threadIdx.x;
    const int r = tid & 127, gh = tid >> 7;
    const size_t row0 = (size_t)blockIdx.x * (SUBROWS * SUBT);

    // weights, layout [k][24]: gates 0..9 at +0..9, 10..19 at +12..21
    for (int idx = tid; idx < DD * NG; idx += THR1) {
        int g = idx % NG, k = idx / NG;
        ws[k * 24 + (g / 10) * 12 + (g % 10)] = w_ih[g * DD + k];
    }
    if (tid == 0) {
        asm volatile("mbarrier.init.shared.b64 [%0], 1;" :: "r"(mbar0));
        asm volatile("mbarrier.init.shared.b64 [%0], 1;" :: "r"(mbar1));
        asm volatile("fence.proxy.async.shared::cta;" ::: "memory");
    }
    __syncthreads();

    auto issue = [&](int s) {
        uint32_t mb  = (s & 1) ? mbar1 : mbar0;
        uint32_t dst = smb + ((s & 1) ? SM_XB1 : SM_XB0);
        const char* src = (const char*)(x + (row0 + (size_t)s * SUBROWS) * DD);
        asm volatile("mbarrier.arrive.expect_tx.shared.b64 _, [%0], %1;"
                     :: "r"(mb), "r"((uint32_t)SUB_BYTES));
        asm volatile(
            "cp.async.bulk.shared::cluster.global.mbarrier::complete_tx::bytes "
            "[%0], [%1], %2, [%3];"
            :: "r"(dst), "l"(src), "r"((uint32_t)SUB_BYTES), "r"(mb) : "memory");
    };
    if (tid == 0) { issue(0); issue(1); }

    for (int s = 0; s < SUBT; ++s) {
        mbar_wait((s & 1) ? mbar1 : mbar0, (uint32_t)((s >> 1) & 1));
        const float* xr = (const float*)(smem + ((s & 1) ? SM_XB1 : SM_XB0)) + r * DD;
        const float* wb = ws + gh * 12;

        ull a0 = 0, a1 = 0, a2 = 0, a3 = 0, a4 = 0;
#pragma unroll 4
        for (int kp = 0; kp < 89; ++kp) {
            float2 x2 = *(const float2*)(xr + 2 * kp);
            const float* p0 = wb + (2 * kp) * 24;
            {
                ulonglong2 q01 = *(const ulonglong2*)(p0);
                ulonglong2 q23 = *(const ulonglong2*)(p0 + 4);
                ull q4 = *(const ull*)(p0 + 8);
                ull xd = dup2(x2.x);
                fma2(a0, xd, q01.x); fma2(a1, xd, q01.y);
                fma2(a2, xd, q23.x); fma2(a3, xd, q23.y);
                fma2(a4, xd, q4);
            }
            {
                const float* p1 = p0 + 24;
                ulonglong2 q01 = *(const ulonglong2*)(p1);
                ulonglong2 q23 = *(const ulonglong2*)(p1 + 4);
                ull q4 = *(const ull*)(p1 + 8);
                ull xd = dup2(x2.y);
                fma2(a0, xd, q01.x); fma2(a1, xd, q01.y);
                fma2(a2, xd, q23.x); fma2(a3, xd, q23.y);
                fma2(a4, xd, q4);
            }
        }
        __syncthreads();
        if (tid == 0 && s + 2 < SUBT) issue(s + 2);

        float gs[10];
        unpack2(a0, gs[0], gs[1]); unpack2(a1, gs[2], gs[3]);
        unpack2(a2, gs[4], gs[5]); unpack2(a3, gs[6], gs[7]);
        unpack2(a4, gs[8], gs[9]);
#pragma unroll
        for (int i = 0; i < 10; ++i) {
            int g = gh * 10 + i;
            sc[r * 20 + (g % 5) * 4 + (g / 5)] = gs[i];
        }
        __syncthreads();
        float4* dst = (float4*)(g_xg + (row0 + (size_t)s * SUBROWS) * NG);
        const float4* src4 = (const float4*)sc;
#pragma unroll
        for (int i = tid; i < SUBROWS * NG / 4; i += THR1) dst[i] = src4[i];
    }
}

// Phase 2: recurrence, 5 lanes/seq, 4 seqs/warp, 8-deep register prefetch ring.
__device__ __forceinline__ float sigm(float xv) {
    float e, r;
    asm("ex2.approx.f32 %0, %1;" : "=f"(e) : "f"(-1.4426950408889634f * xv));
    asm("rcp.approx.f32 %0, %1;" : "=f"(r) : "f"(1.0f + e));
    return r;
}
__device__ __forceinline__ float tanha(float xv) {
    float e, r;
    asm("ex2.approx.f32 %0, %1;" : "=f"(e) : "f"(-2.8853900817779268f * xv));
    asm("rcp.approx.f32 %0, %1;" : "=f"(r) : "f"(1.0f + e));
    return fmaf(2.0f, r, -1.0f);
}

extern "C" __global__ void __launch_bounds__(128)
lstm_rec(const float* __restrict__ w_hh, const float* __restrict__ b_ih,
         const float* __restrict__ b_hh, const float* __restrict__ w_fc,
         const float* __restrict__ b_fc, float* __restrict__ out) {
    const int lane = threadIdx.x & 31;
    const int warp = threadIdx.x >> 5;
    const int s    = lane >> 3;
    const int j0   = lane & 7;
    const int j    = (j0 < HH) ? j0 : 0;
    const int seq  = (blockIdx.x * 4 + warp) * 4 + s;

    ull wif[HH], wgo[HH];
#pragma unroll
    for (int m = 0; m < HH; ++m) {
        wif[m] = pack2(w_hh[j * HH + m],            w_hh[(HH + j) * HH + m]);
        wgo[m] = pack2(w_hh[(2 * HH + j) * HH + m], w_hh[(3 * HH + j) * HH + m]);
    }
    const ull bif = pack2(b_ih[j] + b_hh[j], b_ih[HH + j] + b_hh[HH + j]);
    const ull bgo = pack2(b_ih[2 * HH + j] + b_hh[2 * HH + j],
                          b_ih[3 * HH + j] + b_hh[3 * HH + j]);

    const float4* gp4 = (const float4*)g_xg + (size_t)seq * TT * 5 + j;

    float4 rb[8];
#pragma unroll
    for (int p = 0; p < 8; ++p) rb[p] = gp4[p * 5];

    float c = 0.0f, h = 0.0f;
    ull hv2[HH];
#pragma unroll
    for (int m = 0; m < HH; ++m) hv2[m] = 0ULL;

    for (int t0 = 0; t0 < TT; t0 += 8) {
#pragma unroll
        for (int p = 0; p < 8; ++p) {
            float4 cur = rb[p];
            int tn = t0 + p + 8;
            if (tn < TT) rb[p] = gp4[(size_t)tn * 5];

            ull pif = add2(pack2(cur.x, cur.y), bif);
            ull pgo = add2(pack2(cur.z, cur.w), bgo);
#pragma unroll
            for (int m = 0; m < HH; ++m) {
                fma2(pif, hv2[m], wif[m]);
                fma2(pgo, hv2[m], wgo[m]);
            }
            float pi, pf, pg, po;
            unpack2(pif, pi, pf);
            unpack2(pgo, pg, po);
            float ig = sigm(pi) * tanha(pg);
            c = fmaf(sigm(pf), c, ig);
            h = sigm(po) * tanha(c);
            const int base = lane & ~7;
#pragma unroll
            for (int m = 0; m < HH; ++m)
                hv2[m] = dup2(__shfl_sync(0xffffffffu, h, base + m));
        }
    }

    if (j0 < HH) {
        float acc = b_fc[j];
#pragma unroll
        for (int m = 0; m < HH; ++m) {
            float lo, hi;
            unpack2(hv2[m], lo, hi);
            acc = fmaf(fmaxf(lo, 0.0f), w_fc[j * HH + m], acc);
        }
        out[(size_t)seq * HH + j] = acc;
    }
}

extern "C" void kernel_launch(void* const* d_in, const int* in_sizes, int n_in,
                              void* d_out, int out_size) {
    const float* x    = (const float*)d_in[0];
    const float* w_ih = (const float*)d_in[1];
    const float* w_hh = (const float*)d_in[2];
    const float* b_ih = (const float*)d_in[3];
    const float* b_hh = (const float*)d_in[4];
    const float* w_fc = (const float*)d_in[5];
    const float* b_fc = (const float*)d_in[6];

    cudaFuncSetAttribute(gate_gemm, cudaFuncAttributeMaxDynamicSharedMemorySize, SM_TOT);
    gate_gemm<<<(BB * TT) / (SUBROWS * SUBT), THR1, SM_TOT>>>(x, w_ih);
    lstm_rec<<<BB / 16, 128>>>(w_hh, b_ih, b_hh, w_fc, b_fc, (float*)d_out);
}

// round 5
// speedup vs baseline: 2.6285x; 1.1422x over previous
#include <cuda_runtime.h>
#include <cstdint>

#define BB 2048
#define TT 512
#define DD 178
#define HH 5
#define NG 20
#define SUBROWS 128
#define SUBT 8
#define THR1 128
#define SUB_BYTES (SUBROWS * DD * 4)   // 91136 B

typedef unsigned long long ull;

__device__ float g_xg[(size_t)BB * TT * NG];   // [b][t][j][i,f,g,o], bias folded in

// smem layout (bytes)
#define SM_MBAR 0
#define SM_W    128                      // 178 * 96 B = 17088
#define SM_XB0  17280
#define SM_XB1  (17280 + SUB_BYTES)      // 108416
#define SM_TOT  (SM_XB1 + SUB_BYTES)     // 199552

__device__ __forceinline__ ull pack2(float lo, float hi) {
    ull r; asm("mov.b64 %0, {%1,%2};" : "=l"(r) : "f"(lo), "f"(hi)); return r;
}
__device__ __forceinline__ ull dup2(float v) {
    ull r; asm("mov.b64 %0, {%1,%1};" : "=l"(r) : "f"(v)); return r;
}
__device__ __forceinline__ void unpack2(ull v, float& lo, float& hi) {
    asm("mov.b64 {%0,%1}, %2;" : "=f"(lo), "=f"(hi) : "l"(v));
}
__device__ __forceinline__ void fma2(ull& d, ull a, ull b) {
    asm("fma.rn.f32x2 %0, %1, %2, %0;" : "+l"(d) : "l"(a), "l"(b));
}
__device__ __forceinline__ void mbar_wait(uint32_t mbar, uint32_t parity) {
    asm volatile(
        "{\n\t.reg .pred P;\nW%=:\n\t"
        "mbarrier.try_wait.parity.acquire.cta.shared::cta.b64 P, [%0], %1, 0x989680;\n\t"
        "@P bra D%=;\n\tbra W%=;\nD%=:\n\t}"
        :: "r"(mbar), "r"(parity) : "memory");
}

// ---------------------------------------------------------------------------
// Phase 1: xg = x @ w_ih.T + (b_ih + b_hh), M = 1M rows, K = 178, N = 20.
// Thread = (2 rows) x (one class-pair: gh0 -> (i,f), gh1 -> (g,o)).
// f32x2 lanes = the two gate classes for unit j. Accumulator IS the output
// record pair -> direct STG.64 epilogue. x streamed by bulk TMA, 2 buffers.
// ---------------------------------------------------------------------------
extern "C" __global__ void __launch_bounds__(THR1, 1)
gate_gemm(const float* __restrict__ x, const float* __restrict__ w_ih,
          const float* __restrict__ b_ih, const float* __restrict__ b_hh) {
    extern __shared__ char smem[];
    ull* wsu = (ull*)(smem + SM_W);      // [k][12 ull]: gh0 slots 0-4, gh1 slots 6-10
    const uint32_t smb = (uint32_t)__cvta_generic_to_shared(smem);
    const uint32_t mbar0 = smb + SM_MBAR, mbar1 = mbar0 + 8;
    const int tid = threadIdx.x;
    const int r = tid & 63, gh = tid >> 6;
    const size_t row0 = (size_t)blockIdx.x * (SUBROWS * SUBT);

    // weights: pair (class 2gh, class 2gh+1) for unit j at slot gh*6+j
    for (int idx = tid; idx < DD * 10; idx += THR1) {
        int k = idx / 10, q = idx % 10, g2 = q / 5, j = q % 5;
        wsu[k * 12 + g2 * 6 + j] =
            pack2(w_ih[(g2 * 10 + j) * DD + k], w_ih[(g2 * 10 + 5 + j) * DD + k]);
    }
    // bias pairs for this thread's class-pair
    ull bias[5];
#pragma unroll
    for (int j = 0; j < 5; ++j) {
        int c0 = gh * 10 + j, c1 = gh * 10 + 5 + j;
        bias[j] = pack2(b_ih[c0] + b_hh[c0], b_ih[c1] + b_hh[c1]);
    }
    if (tid == 0) {
        asm volatile("mbarrier.init.shared.b64 [%0], 1;" :: "r"(mbar0));
        asm volatile("mbarrier.init.shared.b64 [%0], 1;" :: "r"(mbar1));
        asm volatile("fence.proxy.async.shared::cta;" ::: "memory");
    }
    __syncthreads();

    auto issue = [&](int s) {
        uint32_t mb  = (s & 1) ? mbar1 : mbar0;
        uint32_t dst = smb + ((s & 1) ? SM_XB1 : SM_XB0);
        const char* src = (const char*)(x + (row0 + (size_t)s * SUBROWS) * DD);
        asm volatile("mbarrier.arrive.expect_tx.shared.b64 _, [%0], %1;"
                     :: "r"(mb), "r"((uint32_t)SUB_BYTES));
        asm volatile(
            "cp.async.bulk.shared::cluster.global.mbarrier::complete_tx::bytes "
            "[%0], [%1], %2, [%3];"
            :: "r"(dst), "l"(src), "r"((uint32_t)SUB_BYTES), "r"(mb) : "memory");
    };
    if (tid == 0) { issue(0); issue(1); }

    const ull* wg = wsu + gh * 6;

    for (int s = 0; s < SUBT; ++s) {
        mbar_wait((s & 1) ? mbar1 : mbar0, (uint32_t)((s >> 1) & 1));
        const float* xb = (const float*)(smem + ((s & 1) ? SM_XB1 : SM_XB0));
        const float* xrA = xb + r * DD;
        const float* xrB = xb + (r + 64) * DD;

        ull acc[10];
#pragma unroll
        for (int j = 0; j < 5; ++j) { acc[j] = bias[j]; acc[5 + j] = bias[j]; }

#pragma unroll 2
        for (int kp = 0; kp < 89; ++kp) {
            float2 xa = *(const float2*)(xrA + 2 * kp);
            float2 xb2 = *(const float2*)(xrB + 2 * kp);
#pragma unroll
            for (int half = 0; half < 2; ++half) {
                const ull* wp = wg + (2 * kp + half) * 12;
                ulonglong2 q01 = *(const ulonglong2*)(wp);
                ulonglong2 q23 = *(const ulonglong2*)(wp + 2);
                ull q4 = wp[4];
                ull xA = dup2(half ? xa.y : xa.x);
                ull xB = dup2(half ? xb2.y : xb2.x);
                fma2(acc[0], xA, q01.x); fma2(acc[1], xA, q01.y);
                fma2(acc[2], xA, q23.x); fma2(acc[3], xA, q23.y);
                fma2(acc[4], xA, q4);
                fma2(acc[5], xB, q01.x); fma2(acc[6], xB, q01.y);
                fma2(acc[7], xB, q23.x); fma2(acc[8], xB, q23.y);
                fma2(acc[9], xB, q4);
            }
        }
        __syncthreads();                       // all reads of this buffer done
        if (tid == 0 && s + 2 < SUBT) issue(s + 2);

        // direct epilogue: acc[j] is the (class-pair) 8B chunk of the record
        size_t rowA = row0 + (size_t)s * SUBROWS + r;
        char* baseA = (char*)(g_xg + rowA * NG) + gh * 8;
        char* baseB = (char*)(g_xg + (rowA + 64) * NG) + gh * 8;
#pragma unroll
        for (int j = 0; j < 5; ++j) {
            *(ull*)(baseA + j * 16) = acc[j];
            *(ull*)(baseB + j * 16) = acc[5 + j];
        }
    }
}

// ---------------------------------------------------------------------------
// Phase 2: recurrence, 5 lanes/seq, 4 seqs/warp, 8-deep register prefetch
// ring. Biases already folded into g_xg by phase 1.
// ---------------------------------------------------------------------------
__device__ __forceinline__ float sigm(float xv) {
    float e, r;
    asm("ex2.approx.f32 %0, %1;" : "=f"(e) : "f"(-1.4426950408889634f * xv));
    asm("rcp.approx.f32 %0, %1;" : "=f"(r) : "f"(1.0f + e));
    return r;
}
__device__ __forceinline__ float tanha(float xv) {
    float e, r;
    asm("ex2.approx.f32 %0, %1;" : "=f"(e) : "f"(-2.8853900817779268f * xv));
    asm("rcp.approx.f32 %0, %1;" : "=f"(r) : "f"(1.0f + e));
    return fmaf(2.0f, r, -1.0f);
}

extern "C" __global__ void __launch_bounds__(128)
lstm_rec(const float* __restrict__ w_hh, const float* __restrict__ w_fc,
         const float* __restrict__ b_fc, float* __restrict__ out) {
    const int lane = threadIdx.x & 31;
    const int warp = threadIdx.x >> 5;
    const int s    = lane >> 3;
    const int j0   = lane & 7;
    const int j    = (j0 < HH) ? j0 : 0;
    const int seq  = (blockIdx.x * 4 + warp) * 4 + s;

    ull wif[HH], wgo[HH];
#pragma unroll
    for (int m = 0; m < HH; ++m) {
        wif[m] = pack2(w_hh[j * HH + m],            w_hh[(HH + j) * HH + m]);
        wgo[m] = pack2(w_hh[(2 * HH + j) * HH + m], w_hh[(3 * HH + j) * HH + m]);
    }

    const float4* gp4 = (const float4*)g_xg + (size_t)seq * TT * 5 + j;

    float4 rb[8];
#pragma unroll
    for (int p = 0; p < 8; ++p) rb[p] = gp4[p * 5];

    float c = 0.0f, h = 0.0f;
    ull hv2[HH];
#pragma unroll
    for (int m = 0; m < HH; ++m) hv2[m] = 0ULL;

    for (int t0 = 0; t0 < TT; t0 += 8) {
#pragma unroll
        for (int p = 0; p < 8; ++p) {
            float4 cur = rb[p];
            int tn = t0 + p + 8;
            if (tn < TT) rb[p] = gp4[(size_t)tn * 5];

            ull pif = pack2(cur.x, cur.y);   // (i,f) with bias folded
            ull pgo = pack2(cur.z, cur.w);   // (g,o) with bias folded
#pragma unroll
            for (int m = 0; m < HH; ++m) {
                fma2(pif, hv2[m], wif[m]);
                fma2(pgo, hv2[m], wgo[m]);
            }
            float pi, pf, pg, po;
            unpack2(pif, pi, pf);
            unpack2(pgo, pg, po);
            float ig = sigm(pi) * tanha(pg);
            c = fmaf(sigm(pf), c, ig);
            h = sigm(po) * tanha(c);
            const int base = lane & ~7;
#pragma unroll
            for (int m = 0; m < HH; ++m)
                hv2[m] = dup2(__shfl_sync(0xffffffffu, h, base + m));
        }
    }

    if (j0 < HH) {
        float acc = b_fc[j];
#pragma unroll
        for (int m = 0; m < HH; ++m) {
            float lo, hi;
            unpack2(hv2[m], lo, hi);
            acc = fmaf(fmaxf(lo, 0.0f), w_fc[j * HH + m], acc);
        }
        out[(size_t)seq * HH + j] = acc;
    }
}

extern "C" void kernel_launch(void* const* d_in, const int* in_sizes, int n_in,
                              void* d_out, int out_size) {
    const float* x    = (const float*)d_in[0];
    const float* w_ih = (const float*)d_in[1];
    const float* w_hh = (const float*)d_in[2];
    const float* b_ih = (const float*)d_in[3];
    const float* b_hh = (const float*)d_in[4];
    const float* w_fc = (const float*)d_in[5];
    const float* b_fc = (const float*)d_in[6];

    cudaFuncSetAttribute(gate_gemm, cudaFuncAttributeMaxDynamicSharedMemorySize, SM_TOT);
    gate_gemm<<<(BB * TT) / (SUBROWS * SUBT), THR1, SM_TOT>>>(x, w_ih, b_ih, b_hh);
    lstm_rec<<<BB / 16, 128>>>(w_hh, w_fc, b_fc, (float*)d_out);
}